// round 8
// baseline (speedup 1.0000x reference)
#include <cuda_runtime.h>
#include <cuda_bf16.h>

// Problem shape (fixed): x = (2, 9, 64, 192, 192) f32
#define NPB 2359296                // voxels per batch = 64*192*192
#define NB  2
#define NVOX (NB * NPB)            // 4,718,592
#define VPT 8                      // voxels per thread (one v8 load per stream)
#define NTHREADS (NVOX / VPT)      // 589,824
#define BLOCK 256

// 256-bit global load/store (sm_100a). Indivisible: guarantees front-batched
// MLP and 2048B contiguous per warp per stream.
__device__ __forceinline__ void ldg256(const float* p, float* d)
{
    asm volatile("ld.global.v8.f32 {%0,%1,%2,%3,%4,%5,%6,%7}, [%8];"
                 : "=f"(d[0]), "=f"(d[1]), "=f"(d[2]), "=f"(d[3]),
                   "=f"(d[4]), "=f"(d[5]), "=f"(d[6]), "=f"(d[7])
                 : "l"(p));
}
__device__ __forceinline__ void stg256(float* p, const float* s)
{
    asm volatile("st.global.v8.f32 [%0], {%1,%2,%3,%4,%5,%6,%7,%8};"
                 :: "l"(p),
                    "f"(s[0]), "f"(s[1]), "f"(s[2]), "f"(s[3]),
                    "f"(s[4]), "f"(s[5]), "f"(s[6]), "f"(s[7])
                 : "memory");
}

// Closed-form symmetric 3x3 eigenvalues (Smith's trigonometric method).
// Returns ascending e0 <= e1 <= e2.
__device__ __forceinline__ void eig3(
    float a00, float a01, float a02, float a11, float a12, float a22,
    float& e0, float& e1, float& e2)
{
    float q  = (a00 + a11 + a22) * (1.0f / 3.0f);
    float d0 = a00 - q, d1 = a11 - q, d2 = a22 - q;
    float off = a01 * a01 + a02 * a02 + a12 * a12;
    float p2  = d0 * d0 + d1 * d1 + d2 * d2 + 2.0f * off;
    p2 = fmaxf(p2, 1e-30f);                 // guard p2==0 (A == q*I)
    float p2s  = p2 * (1.0f / 6.0f);
    float pinv = rsqrtf(p2s);               // MUFU.RSQ
    float p    = p2s * pinv;                // sqrt(p2/6)

    float det = d0 * (d1 * d2 - a12 * a12)
              - a01 * (a01 * d2 - a12 * a02)
              + a02 * (a01 * a12 - d1 * a02);

    float pinv3 = pinv * pinv * pinv;
    float r = 0.5f * det * pinv3;           // det(B)/2, B=(A-qI)/p
    r = fminf(fmaxf(r, -1.0f), 1.0f);

    float theta = acosf(r) * (1.0f / 3.0f); // theta in [0, pi/3]
    float s, c;
    __sincosf(theta, &s, &c);               // s >= 0 on this range

    float t3    = 1.7320508075688772f * s;  // sqrt(3)*sin
    float b_hi  = 2.0f * c;
    float b_lo  = -c - t3;
    float b_mid = -c + t3;

    e0 = fmaf(p, b_lo,  q);
    e1 = fmaf(p, b_mid, q);
    e2 = fmaf(p, b_hi,  q);
}

__global__ void __launch_bounds__(BLOCK)
eigvals_kernel(const float* __restrict__ x, float* __restrict__ out)
{
    int t = blockIdx.x * BLOCK + threadIdx.x;      // [0, NTHREADS)
    const int npb8 = NPB / VPT;                    // 294,912
    int b  = (t >= npb8) ? 1 : 0;                  // NB == 2
    int n8 = t - b * npb8;                         // voxel-group within batch

    const float* base = x + (size_t)b * 9 * NPB + (size_t)n8 * VPT;

    // 9 channel planes, one indivisible 256-bit load each (MLP=9, 2KB/warp/stream)
    float v[9][8];
#pragma unroll
    for (int c = 0; c < 9; ++c)
        ldg256(base + (size_t)c * NPB, v[c]);

    float e[24];                                    // (voxel, 3) packed
#pragma unroll
    for (int j = 0; j < VPT; ++j) {
        float m0 = v[0][j], m1 = v[1][j], m2 = v[2][j];
        float m3 = v[3][j], m4 = v[4][j], m5 = v[5][j];
        float m6 = v[6][j], m7 = v[7][j], m8 = v[8][j];
        // symmetrize: channels are row-major 3x3
        float s01 = 0.5f * (m1 + m3);
        float s02 = 0.5f * (m2 + m6);
        float s12 = 0.5f * (m5 + m7);
        eig3(m0, s01, s02, m4, s12, m8, e[3 * j], e[3 * j + 1], e[3 * j + 2]);
    }

    // out layout: (voxel, 3) ascending; base voxel divisible by 8
    // -> byte offset divisible by 96 -> 32B-aligned; 3x STG.256.
    float* op = out + ((size_t)b * NPB + (size_t)n8 * VPT) * 3;
    stg256(op,      e);
    stg256(op + 8,  e + 8);
    stg256(op + 16, e + 16);
}

extern "C" void kernel_launch(void* const* d_in, const int* in_sizes, int n_in,
                              void* d_out, int out_size)
{
    const float* x = (const float*)d_in[0];
    float* out = (float*)d_out;
    (void)in_sizes; (void)n_in; (void)out_size;
    eigvals_kernel<<<NTHREADS / BLOCK, BLOCK>>>(x, out);
}